// round 9
// baseline (speedup 1.0000x reference)
#include <cuda_runtime.h>
#include <cuda_bf16.h>
#include <math.h>

// ---------------------------------------------------------------------------
// ConvNet: conv(3->16,5x5) -> hermite -> pool2 -> conv(16->16,5x5) -> hermite
//          -> pool2 -> FC(2704->10).  B=512, input 3x64x64.
// Round 8 (re-bench of R7 after infra failure): 2co x (1 pooled row x 2
// pooled cols) thread tile.
//   - input rows: 2x LDS.128 each (16B aligned), parity double-buffer, no MOV
//   - weights padded [co][cin][ky][8]: LDS.128+LDS.32, warp-uniform broadcast
//   - 8 warp-aligned groups x 96 threads = 768-thr CTAs, 2 CTA/SM, 75% occ
// ---------------------------------------------------------------------------

#define B_IMG 512

__device__ float g_pool1[B_IMG * 16 * 30 * 30];   // after conv1+herm+pool
__device__ float g_pool2[B_IMG * 16 * 13 * 13];   // after conv2+herm+pool

__device__ __forceinline__ float herm4(float x, float a0, float a1, float a2,
                                       float a3, float a4) {
    return fmaf(fmaf(fmaf(fmaf(a4, x, a3), x, a2), x, a1), x, a0);
}

// One ky step: 2 output channels, 8 positions (2 conv rows x 4 conv cols).
// T = input row oy+ky, Bt = input row oy+ky+1. costr = co stride in s_w.
// acc[co][j]   = conv(row oy,   col ox+j)
// acc[co][4+j] = conv(row oy+1, col ox+j)
__device__ __forceinline__ void fma_ky(float acc[2][8], const float* wb,
                                       int costr, int ky,
                                       const float* T, const float* Bt) {
    #pragma unroll
    for (int co = 0; co < 2; co++) {
        const float* wr = wb + co * costr + ky * 8;
        float wk[5];
        *(float4*)&wk[0] = *(const float4*)wr;
        wk[4] = wr[4];
        #pragma unroll
        for (int kx = 0; kx < 5; kx++) {
            #pragma unroll
            for (int j = 0; j < 4; j++) {
                acc[co][j]     = fmaf(T[kx + j],  wk[kx], acc[co][j]);
                acc[co][4 + j] = fmaf(Bt[kx + j], wk[kx], acc[co][4 + j]);
            }
        }
    }
}

// ---------------------------------------------------------------------------
// Kernel 1: conv1 + bias + hermite + maxpool2
// Grid: 512 images * 5 bands (6 pooled rows). 768 thr = 8 groups x 96 (90 act).
// Group g -> output channels [2g, 2g+2). Thread: 1 pooled row x 2 pooled cols.
// Smem: padded weights 1920 + input 3*16*64=3072 + bias 16  (~20 KB).
// ---------------------------------------------------------------------------
__global__ void __launch_bounds__(768, 2)
conv1_fused_kernel(const float* __restrict__ x,
                   const float* __restrict__ coef,
                   const float* __restrict__ w,
                   const float* __restrict__ bias) {
    extern __shared__ float smem[];
    float* s_w  = smem;                           // 1920
    float* s_in = smem + 1920;                    // 3072
    float* s_b  = s_in + 3072;                    // 16

    const int img  = blockIdx.x / 5;
    const int band = blockIdx.x % 5;
    const int tid  = threadIdx.x;                 // 768

    const float* xim = x + (size_t)img * 3 * 64 * 64;
    const int row0 = band * 12;
    for (int i = tid; i < 3 * 16 * 64; i += 768) {
        int c   = i >> 10;
        int rem = i & 1023;
        s_in[i] = xim[c * 4096 + row0 * 64 + rem];
    }
    for (int i = tid; i < 1200; i += 768) {
        int co  = i / 75;
        int r   = i % 75;
        int cin = r / 25;
        int r2  = r % 25;
        s_w[((co * 3 + cin) * 5 + (r2 / 5)) * 8 + (r2 % 5)] = w[i];
    }
    if (tid < 16) s_b[tid] = bias[tid];
    __syncthreads();

    const int g = tid / 96;                       // warp-aligned group
    const int t = tid % 96;

    if (t < 90) {
        const int pr  = t / 15;                   // pooled row in band 0..5
        const int pc  = t % 15;                   // pooled col pair 0..14
        const int oy  = 2 * pr;
        const int ox  = 4 * pc;                   // 16B aligned
        const int co0 = 2 * g;

        float acc[2][8];
        #pragma unroll
        for (int co = 0; co < 2; co++) {
            float bv = s_b[co0 + co];
            #pragma unroll
            for (int j = 0; j < 8; j++) acc[co][j] = bv;
        }

        #pragma unroll 1
        for (int cin = 0; cin < 3; cin++) {
            const float* rp = s_in + cin * 1024 + oy * 64 + ox;
            const float* wb = s_w + (co0 * 3 + cin) * 40;   // co stride 120
            float ra[8], rb[8];
            *(float4*)&ra[0] = *(const float4*)rp;
            *(float4*)&ra[4] = *(const float4*)(rp + 4);
            *(float4*)&rb[0] = *(const float4*)(rp + 64);
            *(float4*)&rb[4] = *(const float4*)(rp + 68);
            fma_ky(acc, wb, 120, 0, ra, rb);
            *(float4*)&ra[0] = *(const float4*)(rp + 128);
            *(float4*)&ra[4] = *(const float4*)(rp + 132);
            fma_ky(acc, wb, 120, 1, rb, ra);
            *(float4*)&rb[0] = *(const float4*)(rp + 192);
            *(float4*)&rb[4] = *(const float4*)(rp + 196);
            fma_ky(acc, wb, 120, 2, ra, rb);
            *(float4*)&ra[0] = *(const float4*)(rp + 256);
            *(float4*)&ra[4] = *(const float4*)(rp + 260);
            fma_ky(acc, wb, 120, 3, rb, ra);
            *(float4*)&rb[0] = *(const float4*)(rp + 320);
            *(float4*)&rb[4] = *(const float4*)(rp + 324);
            fma_ky(acc, wb, 120, 4, ra, rb);
        }

        const float c0 = __ldg(coef + 0), c1 = __ldg(coef + 1),
                    c2 = __ldg(coef + 2), c3 = __ldg(coef + 3),
                    c4 = __ldg(coef + 4);
        const float a0 = c0 - 2.0f * c2 + 12.0f * c4;
        const float a1 = 2.0f * c1 - 12.0f * c3;
        const float a2 = 4.0f * c2 - 48.0f * c4;
        const float a3 = 8.0f * c3;
        const float a4 = 16.0f * c4;

        const int py = band * 6 + pr;
        #pragma unroll
        for (int co = 0; co < 2; co++) {
            float h0 = herm4(acc[co][0], a0, a1, a2, a3, a4);
            float h1 = herm4(acc[co][1], a0, a1, a2, a3, a4);
            float h2 = herm4(acc[co][2], a0, a1, a2, a3, a4);
            float h3 = herm4(acc[co][3], a0, a1, a2, a3, a4);
            float h4 = herm4(acc[co][4], a0, a1, a2, a3, a4);
            float h5 = herm4(acc[co][5], a0, a1, a2, a3, a4);
            float h6 = herm4(acc[co][6], a0, a1, a2, a3, a4);
            float h7 = herm4(acc[co][7], a0, a1, a2, a3, a4);
            float m0 = fmaxf(fmaxf(h0, h1), fmaxf(h4, h5));
            float m1 = fmaxf(fmaxf(h2, h3), fmaxf(h6, h7));
            int base = ((img * 16 + co0 + co) * 30 + py) * 30;
            g_pool1[base + 2 * pc]     = m0;
            g_pool1[base + 2 * pc + 1] = m1;
        }
    }
}

// ---------------------------------------------------------------------------
// Kernel 2: conv2 + bias + hermite + maxpool2
// Grid: 512 blocks (one image). 768 thr = 8 groups x 96 (91 active).
// Thread: 2co x 1 pooled row x 2 pooled cols (last pair col-masked).
// Smem: padded weights 10240 + input 16 x 30 rows x stride 32 (zero-padded
//       cols 30,31) = 15360 + bias = ~102.5 KB -> 2 CTA/SM.
// ---------------------------------------------------------------------------
__global__ void __launch_bounds__(768, 2)
conv2_fused_kernel(const float* __restrict__ coef,
                   const float* __restrict__ w,
                   const float* __restrict__ bias) {
    extern __shared__ float smem[];
    float* s_w  = smem;                           // 10240
    float* s_in = smem + 10240;                   // 15360 (stride-32 rows)
    float* s_b  = s_in + 15360;                   // 16

    const int img = blockIdx.x;
    const int tid = threadIdx.x;                  // 768

    const float* xim = g_pool1 + (size_t)img * 14400;
    for (int i = tid; i < 15360; i += 768) {
        int cin = i / 960;
        int row = (i % 960) >> 5;
        int col = i & 31;
        s_in[i] = (col < 30) ? xim[cin * 900 + row * 30 + col] : 0.0f;
    }
    for (int i = tid; i < 6400; i += 768) {
        int co  = i / 400;
        int r   = i % 400;
        int cin = r / 25;
        int r2  = r % 25;
        s_w[((co * 16 + cin) * 5 + (r2 / 5)) * 8 + (r2 % 5)] = w[i];
    }
    if (tid < 16) s_b[tid] = bias[tid];
    __syncthreads();

    const int g = tid / 96;
    const int t = tid % 96;

    if (t < 91) {
        const int pr  = t / 7;                    // pooled row 0..12
        const int pc  = t % 7;                    // pooled col pair 0..6
        const int oy  = 2 * pr;
        const int ox  = 4 * pc;                   // 16B aligned
        const int co0 = 2 * g;

        float acc[2][8];
        #pragma unroll
        for (int co = 0; co < 2; co++) {
            float bv = s_b[co0 + co];
            #pragma unroll
            for (int j = 0; j < 8; j++) acc[co][j] = bv;
        }

        #pragma unroll 1
        for (int cin = 0; cin < 16; cin++) {
            const float* rp = s_in + cin * 960 + oy * 32 + ox;
            const float* wb = s_w + (co0 * 16 + cin) * 40;  // co stride 640
            float ra[8], rb[8];
            *(float4*)&ra[0] = *(const float4*)rp;
            *(float4*)&ra[4] = *(const float4*)(rp + 4);
            *(float4*)&rb[0] = *(const float4*)(rp + 32);
            *(float4*)&rb[4] = *(const float4*)(rp + 36);
            fma_ky(acc, wb, 640, 0, ra, rb);
            *(float4*)&ra[0] = *(const float4*)(rp + 64);
            *(float4*)&ra[4] = *(const float4*)(rp + 68);
            fma_ky(acc, wb, 640, 1, rb, ra);
            *(float4*)&rb[0] = *(const float4*)(rp + 96);
            *(float4*)&rb[4] = *(const float4*)(rp + 100);
            fma_ky(acc, wb, 640, 2, ra, rb);
            *(float4*)&ra[0] = *(const float4*)(rp + 128);
            *(float4*)&ra[4] = *(const float4*)(rp + 132);
            fma_ky(acc, wb, 640, 3, rb, ra);
            *(float4*)&rb[0] = *(const float4*)(rp + 160);
            *(float4*)&rb[4] = *(const float4*)(rp + 164);
            fma_ky(acc, wb, 640, 4, ra, rb);
        }

        const float c0 = __ldg(coef + 0), c1 = __ldg(coef + 1),
                    c2 = __ldg(coef + 2), c3 = __ldg(coef + 3),
                    c4 = __ldg(coef + 4);
        const float a0 = c0 - 2.0f * c2 + 12.0f * c4;
        const float a1 = 2.0f * c1 - 12.0f * c3;
        const float a2 = 4.0f * c2 - 48.0f * c4;
        const float a3 = 8.0f * c3;
        const float a4 = 16.0f * c4;

        #pragma unroll
        for (int co = 0; co < 2; co++) {
            float h0 = herm4(acc[co][0], a0, a1, a2, a3, a4);
            float h1 = herm4(acc[co][1], a0, a1, a2, a3, a4);
            float h2 = herm4(acc[co][2], a0, a1, a2, a3, a4);
            float h3 = herm4(acc[co][3], a0, a1, a2, a3, a4);
            float h4 = herm4(acc[co][4], a0, a1, a2, a3, a4);
            float h5 = herm4(acc[co][5], a0, a1, a2, a3, a4);
            float h6 = herm4(acc[co][6], a0, a1, a2, a3, a4);
            float h7 = herm4(acc[co][7], a0, a1, a2, a3, a4);
            float m0 = fmaxf(fmaxf(h0, h1), fmaxf(h4, h5));
            float m1 = fmaxf(fmaxf(h2, h3), fmaxf(h6, h7));
            int base = ((img * 16 + co0 + co) * 13 + pr) * 13;
            g_pool2[base + 2 * pc] = m0;
            if (2 * pc + 1 < 13) g_pool2[base + 2 * pc + 1] = m1;
        }
    }
}

// ---------------------------------------------------------------------------
// Kernel 3: FC [512,2704] @ [2704,10]^T + bias
// ---------------------------------------------------------------------------
__global__ void __launch_bounds__(128)
fc_kernel(const float* __restrict__ w,
          const float* __restrict__ bias,
          float* __restrict__ out) {
    const int img = blockIdx.x;
    const int tid = threadIdx.x;   // 128

    const float* xv = g_pool2 + (size_t)img * 2704;
    float p[10];
    #pragma unroll
    for (int o = 0; o < 10; o++) p[o] = 0.0f;

    for (int k = tid; k < 2704; k += 128) {
        float v = xv[k];
        #pragma unroll
        for (int o = 0; o < 10; o++) p[o] = fmaf(v, w[o * 2704 + k], p[o]);
    }

    __shared__ float red[4][10];
    const int lane = tid & 31, wrp = tid >> 5;
    #pragma unroll
    for (int o = 0; o < 10; o++) {
        float v = p[o];
        #pragma unroll
        for (int s = 16; s > 0; s >>= 1)
            v += __shfl_down_sync(0xffffffffu, v, s);
        if (lane == 0) red[wrp][o] = v;
    }
    __syncthreads();
    if (tid < 10)
        out[img * 10 + tid] =
            red[0][tid] + red[1][tid] + red[2][tid] + red[3][tid] + bias[tid];
}

// ---------------------------------------------------------------------------
extern "C" void kernel_launch(void* const* d_in, const int* in_sizes, int n_in,
                              void* d_out, int out_size) {
    const float* x       = (const float*)d_in[0];
    const float* coef    = (const float*)d_in[1];
    const float* conv1_w = (const float*)d_in[2];
    const float* conv1_b = (const float*)d_in[3];
    const float* conv2_w = (const float*)d_in[4];
    const float* conv2_b = (const float*)d_in[5];
    const float* fc1_w   = (const float*)d_in[6];
    const float* fc1_b   = (const float*)d_in[7];
    float* out = (float*)d_out;

    const int smem1 = (1920 + 3072 + 16) * sizeof(float);     // ~20 KB
    const int smem2 = (10240 + 15360 + 16) * sizeof(float);   // ~102.5 KB

    cudaFuncSetAttribute(conv2_fused_kernel,
                         cudaFuncAttributeMaxDynamicSharedMemorySize, smem2);

    conv1_fused_kernel<<<B_IMG * 5, 768, smem1>>>(x, coef, conv1_w, conv1_b);
    conv2_fused_kernel<<<B_IMG, 768, smem2>>>(coef, conv2_w, conv2_b);
    fc_kernel<<<B_IMG, 128>>>(fc1_w, fc1_b, out);
}

// round 10
// speedup vs baseline: 1.0067x; 1.0067x over previous
#include <cuda_runtime.h>
#include <cuda_bf16.h>
#include <math.h>

// ---------------------------------------------------------------------------
// ConvNet: conv(3->16,5x5) -> hermite -> pool2 -> conv(16->16,5x5) -> hermite
//          -> pool2 -> FC(2704->10).  B=512, input 3x64x64.
// Round 9: R7 tile (2co x 1 pooled row x 2 pooled cols) with register-safe
// codegen: scalar assigns from named float4 temps (no array address-of),
// macro-expanded ky steps with zero-MOV parity double buffering,
// compile-time weight strides.
// ---------------------------------------------------------------------------

#define B_IMG 512

__device__ float g_pool1[B_IMG * 16 * 30 * 30];   // after conv1+herm+pool
__device__ float g_pool2[B_IMG * 16 * 13 * 13];   // after conv2+herm+pool

__device__ __forceinline__ float herm4(float x, float a0, float a1, float a2,
                                       float a3, float a4) {
    return fmaf(fmaf(fmaf(fmaf(a4, x, a3), x, a2), x, a1), x, a0);
}

// Load 8 consecutive floats at 16B-aligned PTR into array DST via scalar
// assigns from named float4 temps (keeps DST in registers).
#define LOADROW(DST, PTR) do {                                              \
    float4 q_ = *(const float4*)(PTR);                                      \
    DST[0] = q_.x; DST[1] = q_.y; DST[2] = q_.z; DST[3] = q_.w;             \
    q_ = *(const float4*)((PTR) + 4);                                       \
    DST[4] = q_.x; DST[5] = q_.y; DST[6] = q_.z; DST[7] = q_.w;             \
} while (0)

// One ky step: 2 output channels, 8 outputs (2 conv rows x 4 conv cols).
// T = input row oy+KY, Bt = input row oy+KY+1. WB/COSTR compile-time-ish.
#define KY_STEP(KY, T, Bt, WB, COSTR) do {                                  \
    _Pragma("unroll")                                                       \
    for (int co_ = 0; co_ < 2; co_++) {                                     \
        const float* wr_ = (WB) + co_ * (COSTR) + (KY) * 8;                 \
        float4 wq_ = *(const float4*)wr_;                                   \
        float wk_[5];                                                       \
        wk_[0] = wq_.x; wk_[1] = wq_.y; wk_[2] = wq_.z; wk_[3] = wq_.w;     \
        wk_[4] = wr_[4];                                                    \
        _Pragma("unroll")                                                   \
        for (int kx_ = 0; kx_ < 5; kx_++) {                                 \
            _Pragma("unroll")                                               \
            for (int j_ = 0; j_ < 4; j_++) {                                \
                acc[co_][j_]     = fmaf(T[kx_ + j_],  wk_[kx_], acc[co_][j_]);     \
                acc[co_][4 + j_] = fmaf(Bt[kx_ + j_], wk_[kx_], acc[co_][4 + j_]); \
            }                                                               \
        }                                                                   \
    }                                                                       \
} while (0)

// ---------------------------------------------------------------------------
// Kernel 1: conv1 + bias + hermite + maxpool2
// Grid: 512 images * 5 bands (6 pooled rows). 768 thr = 8 groups x 96 (90 act).
// Group g -> output channels [2g, 2g+2). Thread: 1 pooled row x 2 pooled cols.
// Smem: padded weights 1920 + input 3*16*64=3072 + bias 16  (~20 KB).
// ---------------------------------------------------------------------------
__global__ void __launch_bounds__(768, 2)
conv1_fused_kernel(const float* __restrict__ x,
                   const float* __restrict__ coef,
                   const float* __restrict__ w,
                   const float* __restrict__ bias) {
    extern __shared__ float smem[];
    float* s_w  = smem;                           // 1920
    float* s_in = smem + 1920;                    // 3072
    float* s_b  = s_in + 3072;                    // 16

    const int img  = blockIdx.x / 5;
    const int band = blockIdx.x % 5;
    const int tid  = threadIdx.x;                 // 768

    const float* xim = x + (size_t)img * 3 * 64 * 64;
    const int row0 = band * 12;
    for (int i = tid; i < 3 * 16 * 64; i += 768) {
        int c   = i >> 10;
        int rem = i & 1023;
        s_in[i] = xim[c * 4096 + row0 * 64 + rem];
    }
    // pad weights: dst[((co*3+cin)*5+ky)*8 + kx]
    for (int i = tid; i < 1200; i += 768) {
        int co  = i / 75;
        int r   = i % 75;
        int cin = r / 25;
        int r2  = r % 25;
        s_w[((co * 3 + cin) * 5 + (r2 / 5)) * 8 + (r2 % 5)] = w[i];
    }
    if (tid < 16) s_b[tid] = bias[tid];
    __syncthreads();

    const int g = tid / 96;                       // warp-aligned group
    const int t = tid % 96;

    if (t < 90) {
        const int pr  = t / 15;                   // pooled row in band 0..5
        const int pc  = t % 15;                   // pooled col pair 0..14
        const int oy  = 2 * pr;
        const int ox  = 4 * pc;                   // 16B aligned
        const int co0 = 2 * g;

        float acc[2][8];
        #pragma unroll
        for (int co = 0; co < 2; co++) {
            float bv = s_b[co0 + co];
            #pragma unroll
            for (int j = 0; j < 8; j++) acc[co][j] = bv;
        }

        #pragma unroll 1
        for (int cin = 0; cin < 3; cin++) {
            const float* rp = s_in + cin * 1024 + oy * 64 + ox;
            const float* wb = s_w + (co0 * 3 + cin) * 40;   // co stride 120
            float va[8], vb[8];
            LOADROW(va, rp);                      // row oy
            LOADROW(vb, rp + 64);                 // row oy+1
            KY_STEP(0, va, vb, wb, 120);
            LOADROW(va, rp + 128);                // row oy+2
            KY_STEP(1, vb, va, wb, 120);
            LOADROW(vb, rp + 192);                // row oy+3
            KY_STEP(2, va, vb, wb, 120);
            LOADROW(va, rp + 256);                // row oy+4
            KY_STEP(3, vb, va, wb, 120);
            LOADROW(vb, rp + 320);                // row oy+5
            KY_STEP(4, va, vb, wb, 120);
        }

        const float c0 = __ldg(coef + 0), c1 = __ldg(coef + 1),
                    c2 = __ldg(coef + 2), c3 = __ldg(coef + 3),
                    c4 = __ldg(coef + 4);
        const float a0 = c0 - 2.0f * c2 + 12.0f * c4;
        const float a1 = 2.0f * c1 - 12.0f * c3;
        const float a2 = 4.0f * c2 - 48.0f * c4;
        const float a3 = 8.0f * c3;
        const float a4 = 16.0f * c4;

        const int py = band * 6 + pr;
        #pragma unroll
        for (int co = 0; co < 2; co++) {
            float h0 = herm4(acc[co][0], a0, a1, a2, a3, a4);
            float h1 = herm4(acc[co][1], a0, a1, a2, a3, a4);
            float h2 = herm4(acc[co][2], a0, a1, a2, a3, a4);
            float h3 = herm4(acc[co][3], a0, a1, a2, a3, a4);
            float h4 = herm4(acc[co][4], a0, a1, a2, a3, a4);
            float h5 = herm4(acc[co][5], a0, a1, a2, a3, a4);
            float h6 = herm4(acc[co][6], a0, a1, a2, a3, a4);
            float h7 = herm4(acc[co][7], a0, a1, a2, a3, a4);
            float m0 = fmaxf(fmaxf(h0, h1), fmaxf(h4, h5));
            float m1 = fmaxf(fmaxf(h2, h3), fmaxf(h6, h7));
            int base = ((img * 16 + co0 + co) * 30 + py) * 30;
            g_pool1[base + 2 * pc]     = m0;
            g_pool1[base + 2 * pc + 1] = m1;
        }
    }
}

// ---------------------------------------------------------------------------
// Kernel 2: conv2 + bias + hermite + maxpool2
// Grid: 512 blocks (one image). 768 thr = 8 groups x 96 (91 active).
// Thread: 2co x 1 pooled row x 2 pooled cols (last pair col-masked).
// Smem: padded weights 10240 + input 16 x 30 rows x stride 32 (zero-padded
//       cols 30,31) = 15360 + bias = ~102.5 KB -> 2 CTA/SM.
// ---------------------------------------------------------------------------
__global__ void __launch_bounds__(768, 2)
conv2_fused_kernel(const float* __restrict__ coef,
                   const float* __restrict__ w,
                   const float* __restrict__ bias) {
    extern __shared__ float smem[];
    float* s_w  = smem;                           // 10240
    float* s_in = smem + 10240;                   // 15360 (stride-32 rows)
    float* s_b  = s_in + 15360;                   // 16

    const int img = blockIdx.x;
    const int tid = threadIdx.x;                  // 768

    const float* xim = g_pool1 + (size_t)img * 14400;
    for (int i = tid; i < 15360; i += 768) {
        int cin = i / 960;
        int row = (i % 960) >> 5;
        int col = i & 31;
        s_in[i] = (col < 30) ? xim[cin * 900 + row * 30 + col] : 0.0f;
    }
    for (int i = tid; i < 6400; i += 768) {
        int co  = i / 400;
        int r   = i % 400;
        int cin = r / 25;
        int r2  = r % 25;
        s_w[((co * 16 + cin) * 5 + (r2 / 5)) * 8 + (r2 % 5)] = w[i];
    }
    if (tid < 16) s_b[tid] = bias[tid];
    __syncthreads();

    const int g = tid / 96;
    const int t = tid % 96;

    if (t < 91) {
        const int pr  = t / 7;                    // pooled row 0..12
        const int pc  = t % 7;                    // pooled col pair 0..6
        const int oy  = 2 * pr;
        const int ox  = 4 * pc;                   // 16B aligned
        const int co0 = 2 * g;

        float acc[2][8];
        #pragma unroll
        for (int co = 0; co < 2; co++) {
            float bv = s_b[co0 + co];
            #pragma unroll
            for (int j = 0; j < 8; j++) acc[co][j] = bv;
        }

        #pragma unroll 1
        for (int cin = 0; cin < 16; cin++) {
            const float* rp = s_in + cin * 960 + oy * 32 + ox;
            const float* wb = s_w + (co0 * 16 + cin) * 40;  // co stride 640
            float va[8], vb[8];
            LOADROW(va, rp);                      // row oy
            LOADROW(vb, rp + 32);                 // row oy+1
            KY_STEP(0, va, vb, wb, 640);
            LOADROW(va, rp + 64);                 // row oy+2
            KY_STEP(1, vb, va, wb, 640);
            LOADROW(vb, rp + 96);                 // row oy+3
            KY_STEP(2, va, vb, wb, 640);
            LOADROW(va, rp + 128);                // row oy+4
            KY_STEP(3, vb, va, wb, 640);
            LOADROW(vb, rp + 160);                // row oy+5
            KY_STEP(4, va, vb, wb, 640);
        }

        const float c0 = __ldg(coef + 0), c1 = __ldg(coef + 1),
                    c2 = __ldg(coef + 2), c3 = __ldg(coef + 3),
                    c4 = __ldg(coef + 4);
        const float a0 = c0 - 2.0f * c2 + 12.0f * c4;
        const float a1 = 2.0f * c1 - 12.0f * c3;
        const float a2 = 4.0f * c2 - 48.0f * c4;
        const float a3 = 8.0f * c3;
        const float a4 = 16.0f * c4;

        #pragma unroll
        for (int co = 0; co < 2; co++) {
            float h0 = herm4(acc[co][0], a0, a1, a2, a3, a4);
            float h1 = herm4(acc[co][1], a0, a1, a2, a3, a4);
            float h2 = herm4(acc[co][2], a0, a1, a2, a3, a4);
            float h3 = herm4(acc[co][3], a0, a1, a2, a3, a4);
            float h4 = herm4(acc[co][4], a0, a1, a2, a3, a4);
            float h5 = herm4(acc[co][5], a0, a1, a2, a3, a4);
            float h6 = herm4(acc[co][6], a0, a1, a2, a3, a4);
            float h7 = herm4(acc[co][7], a0, a1, a2, a3, a4);
            float m0 = fmaxf(fmaxf(h0, h1), fmaxf(h4, h5));
            float m1 = fmaxf(fmaxf(h2, h3), fmaxf(h6, h7));
            int base = ((img * 16 + co0 + co) * 13 + pr) * 13;
            g_pool2[base + 2 * pc] = m0;
            if (2 * pc + 1 < 13) g_pool2[base + 2 * pc + 1] = m1;
        }
    }
}

// ---------------------------------------------------------------------------
// Kernel 3: FC [512,2704] @ [2704,10]^T + bias
// ---------------------------------------------------------------------------
__global__ void __launch_bounds__(128)
fc_kernel(const float* __restrict__ w,
          const float* __restrict__ bias,
          float* __restrict__ out) {
    const int img = blockIdx.x;
    const int tid = threadIdx.x;   // 128

    const float* xv = g_pool2 + (size_t)img * 2704;
    float p[10];
    #pragma unroll
    for (int o = 0; o < 10; o++) p[o] = 0.0f;

    for (int k = tid; k < 2704; k += 128) {
        float v = xv[k];
        #pragma unroll
        for (int o = 0; o < 10; o++) p[o] = fmaf(v, w[o * 2704 + k], p[o]);
    }

    __shared__ float red[4][10];
    const int lane = tid & 31, wrp = tid >> 5;
    #pragma unroll
    for (int o = 0; o < 10; o++) {
        float v = p[o];
        #pragma unroll
        for (int s = 16; s > 0; s >>= 1)
            v += __shfl_down_sync(0xffffffffu, v, s);
        if (lane == 0) red[wrp][o] = v;
    }
    __syncthreads();
    if (tid < 10)
        out[img * 10 + tid] =
            red[0][tid] + red[1][tid] + red[2][tid] + red[3][tid] + bias[tid];
}

// ---------------------------------------------------------------------------
extern "C" void kernel_launch(void* const* d_in, const int* in_sizes, int n_in,
                              void* d_out, int out_size) {
    const float* x       = (const float*)d_in[0];
    const float* coef    = (const float*)d_in[1];
    const float* conv1_w = (const float*)d_in[2];
    const float* conv1_b = (const float*)d_in[3];
    const float* conv2_w = (const float*)d_in[4];
    const float* conv2_b = (const float*)d_in[5];
    const float* fc1_w   = (const float*)d_in[6];
    const float* fc1_b   = (const float*)d_in[7];
    float* out = (float*)d_out;

    const int smem1 = (1920 + 3072 + 16) * sizeof(float);     // ~20 KB
    const int smem2 = (10240 + 15360 + 16) * sizeof(float);   // ~102.5 KB

    cudaFuncSetAttribute(conv2_fused_kernel,
                         cudaFuncAttributeMaxDynamicSharedMemorySize, smem2);

    conv1_fused_kernel<<<B_IMG * 5, 768, smem1>>>(x, coef, conv1_w, conv1_b);
    conv2_fused_kernel<<<B_IMG, 768, smem2>>>(coef, conv2_w, conv2_b);
    fc_kernel<<<B_IMG, 128>>>(fc1_w, fc1_b, out);
}